// round 8
// baseline (speedup 1.0000x reference)
#include <cuda_runtime.h>
#include <math.h>
#include <cstdint>

#define BATCH 256
#define NT    512
#define NA    32
#define OBS   128
#define ACT   8
#define DV    128
#define DH    64
#define DO    8
#define S1    132   // padded stride (floats) for 128-wide rows, float4-aligned
#define S2    68    // padded stride for 64-wide rows

// ---- SMEM layout (floats) ----
#define OFF_STATES 0
#define OFF_T      (OFF_STATES + NA*S1)
#define OFF_AVA    (OFF_T + NA*S1)
#define OFF_DIFF   (OFF_AVA + NA*S1)
#define OFF_W      (OFF_DIFF + NA*S1)
#define OFF_AW1    (OFF_W + NA*NA)
#define OFF_DW1    (OFF_AW1 + NA*S2)
#define OFF_BW1    (OFF_DW1 + NA*S2)
#define OFF_ACT    (OFF_BW1 + NA*S2)
#define OFF_POL    (OFF_ACT + NA*ACT)
#define OFF_W2     (OFF_POL + NA*ACT)
#define SMEM_FLOATS (OFF_W2 + DH*DO)
#define SMEM_BYTES  (SMEM_FLOATS * 4)

__device__ float g_M[OBS * OBS];   // (Wq @ Wk^T) / sqrt(DK), contract over DK

// ---------------------------------------------------------------------------
// M[i][j] = (sum_d Wq[i][d] * Wk[j][d]) / sqrt(128)
// ---------------------------------------------------------------------------
__global__ void compute_M_kernel(const float* __restrict__ Wq,
                                 const float* __restrict__ Wk) {
    __shared__ float qs[16][OBS + 4];
    __shared__ float ks[16][OBS + 4];
    const int i0 = (blockIdx.x & 7) * 16;
    const int j0 = (blockIdx.x >> 3) * 16;
    const int tid = threadIdx.x;
    for (int idx = tid; idx < 16 * 32; idx += 256) {
        int r = idx >> 5, d4 = (idx & 31) * 4;
        *reinterpret_cast<float4*>(&qs[r][d4]) =
            *reinterpret_cast<const float4*>(&Wq[(i0 + r) * OBS + d4]);
        *reinterpret_cast<float4*>(&ks[r][d4]) =
            *reinterpret_cast<const float4*>(&Wk[(j0 + r) * OBS + d4]);
    }
    __syncthreads();
    const int ti = tid >> 4, tj = tid & 15;
    float acc = 0.f;
    #pragma unroll 8
    for (int d = 0; d < OBS; ++d)
        acc = fmaf(qs[ti][d], ks[tj][d], acc);
    g_M[(i0 + ti) * OBS + j0 + tj] = acc * 0.08838834764831845f;
}

// ---------------------------------------------------------------------------
// Main fused kernel: one CTA per batch element, 512 threads, 2 CTAs/SM
// ---------------------------------------------------------------------------
__global__ __launch_bounds__(NT, 2)
void critic_kernel(const float* __restrict__ states,
                   const float* __restrict__ policies,
                   const float* __restrict__ actions,
                   const float* __restrict__ Wv,
                   const float* __restrict__ W1,
                   const float* __restrict__ W2,
                   float* __restrict__ value_out,
                   float* __restrict__ weight_out)
{
    extern __shared__ float sm[];
    float* s_states = sm + OFF_STATES;
    float* s_t      = sm + OFF_T;
    float* s_avA    = sm + OFF_AVA;
    float* s_diff   = sm + OFF_DIFF;
    float* s_w      = sm + OFF_W;
    float* s_aW1    = sm + OFF_AW1;
    float* s_dW1    = sm + OFF_DW1;
    float* s_bW1    = sm + OFF_BW1;
    float* s_act    = sm + OFF_ACT;
    float* s_pol    = sm + OFF_POL;
    float* s_W2     = sm + OFF_W2;

    const int b   = blockIdx.x;
    const int tid = threadIdx.x;

    // ---- stage inputs ----
    {
        const float* st_b = states + (size_t)b * NA * OBS;
        for (int idx = tid; idx < NA * OBS / 4; idx += NT) {
            int i = idx >> 5, d4 = (idx & 31) * 4;
            *reinterpret_cast<float4*>(&s_states[i * S1 + d4]) =
                *reinterpret_cast<const float4*>(&st_b[i * OBS + d4]);
        }
        for (int idx = tid; idx < NA * ACT; idx += NT) {
            s_act[idx] = actions [(size_t)b * NA * ACT + idx];
            s_pol[idx] = policies[(size_t)b * NA * ACT + idx];
        }
        for (int idx = tid; idx < DH * DO; idx += NT) s_W2[idx] = W2[idx];
    }
    __syncthreads();

    // =========================================================================
    // Phase 1: t = states@M and avA/diff = tanh(concat@Wv).
    // 16 warps: warp w owns cols [8w, 8w+8). Lane: c0 = 8w + (l&1)*4,
    // rows {g, g+16} with g = l>>1. 2 rows x 4 cols per thread.
    // =========================================================================
    {
        const int w  = tid >> 5;          // 0..15
        const int l  = tid & 31;
        const int g  = l >> 1;            // 0..15
        const int c0 = w * 8 + (l & 1) * 4;

        float4 tAcc[2], vAcc[2];
        #pragma unroll
        for (int m = 0; m < 2; ++m) {
            tAcc[m] = make_float4(0.f, 0.f, 0.f, 0.f);
            vAcc[m] = make_float4(0.f, 0.f, 0.f, 0.f);
        }
        for (int kk = 0; kk < OBS; kk += 4) {
            float4 sv[2];
            sv[0] = *reinterpret_cast<const float4*>(&s_states[ g       * S1 + kk]);
            sv[1] = *reinterpret_cast<const float4*>(&s_states[(g + 16) * S1 + kk]);
            #pragma unroll
            for (int t = 0; t < 4; ++t) {
                float4 mq = *reinterpret_cast<const float4*>(&g_M[(kk + t) * OBS + c0]);
                float4 wv = *reinterpret_cast<const float4*>(&Wv [(kk + t) * DV  + c0]);
                #pragma unroll
                for (int m = 0; m < 2; ++m) {
                    float s = reinterpret_cast<const float*>(&sv[m])[t];
                    tAcc[m].x = fmaf(s, mq.x, tAcc[m].x);
                    tAcc[m].y = fmaf(s, mq.y, tAcc[m].y);
                    tAcc[m].z = fmaf(s, mq.z, tAcc[m].z);
                    tAcc[m].w = fmaf(s, mq.w, tAcc[m].w);
                    vAcc[m].x = fmaf(s, wv.x, vAcc[m].x);
                    vAcc[m].y = fmaf(s, wv.y, vAcc[m].y);
                    vAcc[m].z = fmaf(s, wv.z, vAcc[m].z);
                    vAcc[m].w = fmaf(s, wv.w, vAcc[m].w);
                }
            }
        }
        #pragma unroll
        for (int m = 0; m < 2; ++m)
            *reinterpret_cast<float4*>(&s_t[(g + 16 * m) * S1 + c0]) = tAcc[m];

        // action/policy tail (8 extra K) on the shared states partial
        float4 accA[2], accP[2];
        #pragma unroll
        for (int m = 0; m < 2; ++m) { accA[m] = vAcc[m]; accP[m] = vAcc[m]; }
        #pragma unroll
        for (int kk = 0; kk < ACT; ++kk) {
            float4 wv = *reinterpret_cast<const float4*>(&Wv[(OBS + kk) * DV + c0]);
            #pragma unroll
            for (int m = 0; m < 2; ++m) {
                float a = s_act[(g + 16 * m) * ACT + kk];
                float p = s_pol[(g + 16 * m) * ACT + kk];
                accA[m].x = fmaf(a, wv.x, accA[m].x);
                accA[m].y = fmaf(a, wv.y, accA[m].y);
                accA[m].z = fmaf(a, wv.z, accA[m].z);
                accA[m].w = fmaf(a, wv.w, accA[m].w);
                accP[m].x = fmaf(p, wv.x, accP[m].x);
                accP[m].y = fmaf(p, wv.y, accP[m].y);
                accP[m].z = fmaf(p, wv.z, accP[m].z);
                accP[m].w = fmaf(p, wv.w, accP[m].w);
            }
        }
        #pragma unroll
        for (int m = 0; m < 2; ++m) {
            float4 tA, dF;
            tA.x = tanhf(accA[m].x); tA.y = tanhf(accA[m].y);
            tA.z = tanhf(accA[m].z); tA.w = tanhf(accA[m].w);
            dF.x = tanhf(accP[m].x) - tA.x; dF.y = tanhf(accP[m].y) - tA.y;
            dF.z = tanhf(accP[m].z) - tA.z; dF.w = tanhf(accP[m].w) - tA.w;
            *reinterpret_cast<float4*>(&s_avA [(g + 16 * m) * S1 + c0]) = tA;
            *reinterpret_cast<float4*>(&s_diff[(g + 16 * m) * S1 + c0]) = dF;
        }
    }
    __syncthreads();

    // =========================================================================
    // Phase 2a: score[i][j] = t[i,:] . states[j,:]  (scale folded into M).
    // i = tid>>4 (warp w owns rows {2w, 2w+1}), j0 = (tid&15)*2.
    // =========================================================================
    {
        const int i  = tid >> 4;
        const int j0 = (tid & 15) * 2;
        float a0 = 0.f, a1 = 0.f;
        for (int kk = 0; kk < OBS; kk += 4) {
            float4 qi = *reinterpret_cast<const float4*>(&s_t[i * S1 + kk]);
            float4 k0 = *reinterpret_cast<const float4*>(&s_states[ j0      * S1 + kk]);
            float4 k1 = *reinterpret_cast<const float4*>(&s_states[(j0 + 1) * S1 + kk]);
            a0 = fmaf(qi.x, k0.x, fmaf(qi.y, k0.y, fmaf(qi.z, k0.z, fmaf(qi.w, k0.w, a0))));
            a1 = fmaf(qi.x, k1.x, fmaf(qi.y, k1.y, fmaf(qi.z, k1.z, fmaf(qi.w, k1.w, a1))));
        }
        s_w[i * NA + j0]     = a0;
        s_w[i * NA + j0 + 1] = a1;
    }
    __syncwarp();

    // =========================================================================
    // Phase 2a': softmax — warp w owns rows {2w, 2w+1} (warp-local sync only)
    // =========================================================================
    {
        const int warp = tid >> 5, lane = tid & 31;
        #pragma unroll
        for (int rr = 0; rr < 2; ++rr) {
            const int row = warp * 2 + rr;
            float v = s_w[row * NA + lane];
            float m = v;
            #pragma unroll
            for (int off = 16; off > 0; off >>= 1)
                m = fmaxf(m, __shfl_xor_sync(0xffffffffu, m, off));
            float e = expf(v - m);
            float s = e;
            #pragma unroll
            for (int off = 16; off > 0; off >>= 1)
                s += __shfl_xor_sync(0xffffffffu, s, off);
            float w = e / s;
            s_w[row * NA + lane] = w;
            weight_out[(size_t)b * NA * NA + row * NA + lane] = w;
        }
    }

    // =========================================================================
    // Phase 2b: aW1 = avA@W1, dW1 = diff@W1. 1 j-row x 4 h per thread.
    // =========================================================================
    {
        const int j  = tid >> 4;          // 0..31
        const int h0 = (tid & 15) * 4;
        float4 aA = make_float4(0,0,0,0), aD = make_float4(0,0,0,0);
        for (int d = 0; d < DV; d += 4) {
            float4 av = *reinterpret_cast<const float4*>(&s_avA [j * S1 + d]);
            float4 df = *reinterpret_cast<const float4*>(&s_diff[j * S1 + d]);
            #pragma unroll
            for (int t = 0; t < 4; ++t) {
                float4 w1 = *reinterpret_cast<const float4*>(&W1[(d + t) * DH + h0]);
                float a = reinterpret_cast<const float*>(&av)[t];
                float q = reinterpret_cast<const float*>(&df)[t];
                aA.x = fmaf(a, w1.x, aA.x); aA.y = fmaf(a, w1.y, aA.y);
                aA.z = fmaf(a, w1.z, aA.z); aA.w = fmaf(a, w1.w, aA.w);
                aD.x = fmaf(q, w1.x, aD.x); aD.y = fmaf(q, w1.y, aD.y);
                aD.z = fmaf(q, w1.z, aD.z); aD.w = fmaf(q, w1.w, aD.w);
            }
        }
        *reinterpret_cast<float4*>(&s_aW1[j * S2 + h0]) = aA;
        *reinterpret_cast<float4*>(&s_dW1[j * S2 + h0]) = aD;
    }
    __syncthreads();

    // =========================================================================
    // Phase 4: bW1 = w @ aW1   [32 x 64]. 1 a-row x 4 h per thread.
    // =========================================================================
    {
        const int a  = tid >> 4;
        const int h0 = (tid & 15) * 4;
        float4 acc = make_float4(0,0,0,0);
        #pragma unroll
        for (int j = 0; j < NA; j += 4) {
            float4 wq = *reinterpret_cast<const float4*>(&s_w[a * NA + j]);
            #pragma unroll
            for (int t = 0; t < 4; ++t) {
                float4 aw = *reinterpret_cast<const float4*>(&s_aW1[(j + t) * S2 + h0]);
                float v = reinterpret_cast<const float*>(&wq)[t];
                acc.x = fmaf(v, aw.x, acc.x); acc.y = fmaf(v, aw.y, acc.y);
                acc.z = fmaf(v, aw.z, acc.z); acc.w = fmaf(v, aw.w, acc.w);
            }
        }
        *reinterpret_cast<float4*>(&s_bW1[a * S2 + h0]) = acc;
    }
    __syncthreads();

    // =========================================================================
    // Phase 5: per (a,c): h = leaky(bW1[a] + w*dW1[c]); out = h @ W2.
    // 2 a-values per thread ({a0, a0+16}), c = tid&31.
    // =========================================================================
    {
        const int a0 = tid >> 5;      // 0..15
        const int c  = tid & 31;      // 0..31
        float wk[2];
        wk[0] = s_w[ a0       * NA + c];
        wk[1] = s_w[(a0 + 16) * NA + c];

        float4 accL[2], accH[2];
        #pragma unroll
        for (int k = 0; k < 2; ++k) {
            accL[k] = make_float4(0,0,0,0);
            accH[k] = make_float4(0,0,0,0);
        }
        for (int h = 0; h < DH; h += 4) {
            float4 dq = *reinterpret_cast<const float4*>(&s_dW1[c * S2 + h]);
            float4 bq0 = *reinterpret_cast<const float4*>(&s_bW1[ a0       * S2 + h]);
            float4 bq1 = *reinterpret_cast<const float4*>(&s_bW1[(a0 + 16) * S2 + h]);
            #pragma unroll
            for (int t = 0; t < 4; ++t) {
                float4 w2lo = *reinterpret_cast<const float4*>(&s_W2[(h + t) * DO]);
                float4 w2hi = *reinterpret_cast<const float4*>(&s_W2[(h + t) * DO + 4]);
                float dqt = reinterpret_cast<const float*>(&dq)[t];

                float x0 = fmaf(wk[0], dqt, reinterpret_cast<const float*>(&bq0)[t]);
                x0 = fmaxf(x0, 0.01f * x0);
                accL[0].x = fmaf(x0, w2lo.x, accL[0].x);
                accL[0].y = fmaf(x0, w2lo.y, accL[0].y);
                accL[0].z = fmaf(x0, w2lo.z, accL[0].z);
                accL[0].w = fmaf(x0, w2lo.w, accL[0].w);
                accH[0].x = fmaf(x0, w2hi.x, accH[0].x);
                accH[0].y = fmaf(x0, w2hi.y, accH[0].y);
                accH[0].z = fmaf(x0, w2hi.z, accH[0].z);
                accH[0].w = fmaf(x0, w2hi.w, accH[0].w);

                float x1 = fmaf(wk[1], dqt, reinterpret_cast<const float*>(&bq1)[t]);
                x1 = fmaxf(x1, 0.01f * x1);
                accL[1].x = fmaf(x1, w2lo.x, accL[1].x);
                accL[1].y = fmaf(x1, w2lo.y, accL[1].y);
                accL[1].z = fmaf(x1, w2lo.z, accL[1].z);
                accL[1].w = fmaf(x1, w2lo.w, accL[1].w);
                accH[1].x = fmaf(x1, w2hi.x, accH[1].x);
                accH[1].y = fmaf(x1, w2hi.y, accH[1].y);
                accH[1].z = fmaf(x1, w2hi.z, accH[1].z);
                accH[1].w = fmaf(x1, w2hi.w, accH[1].w);
            }
        }
        #pragma unroll
        for (int k = 0; k < 2; ++k) {
            float4* outp = reinterpret_cast<float4*>(
                value_out + (((size_t)b * NA + (a0 + 16 * k)) * NA + c) * DO);
            outp[0] = accL[k];
            outp[1] = accH[k];
        }
    }
}

extern "C" void kernel_launch(void* const* d_in, const int* in_sizes, int n_in,
                              void* d_out, int out_size) {
    const float* states   = (const float*)d_in[0];
    const float* policies = (const float*)d_in[1];
    const float* actions  = (const float*)d_in[2];
    const float* Wk       = (const float*)d_in[3];
    const float* Wq       = (const float*)d_in[4];
    const float* Wv       = (const float*)d_in[5];
    const float* W1       = (const float*)d_in[6];
    const float* W2       = (const float*)d_in[7];

    float* value_out  = (float*)d_out;                              // [B,N,N,8]
    float* weight_out = value_out + (size_t)BATCH * NA * NA * DO;   // [B,N,N]

    compute_M_kernel<<<64, 256>>>(Wq, Wk);

    cudaFuncSetAttribute(critic_kernel,
                         cudaFuncAttributeMaxDynamicSharedMemorySize, SMEM_BYTES);
    critic_kernel<<<BATCH, NT, SMEM_BYTES>>>(
        states, policies, actions, Wv, W1, W2, value_out, weight_out);
}